// round 3
// baseline (speedup 1.0000x reference)
#include <cuda_runtime.h>

#define Bb 4
#define Ss 4096
#define Ee 256
#define Hh 64

// Scratch for projected Q, K, V (device globals: no allocation allowed)
__device__ float g_q[Bb * Ss * Hh];
__device__ float g_k[Bb * Ss * Hh];
__device__ float g_v[Bb * Ss * Hh];

typedef unsigned long long ull;

__device__ __forceinline__ ull ffma2(ull a, ull b, ull c) {
    ull d;
    asm("fma.rn.f32x2 %0, %1, %2, %3;" : "=l"(d) : "l"(a), "l"(b), "l"(c));
    return d;
}
__device__ __forceinline__ ull fmul2(ull a, ull b) {
    ull d;
    asm("mul.rn.f32x2 %0, %1, %2;" : "=l"(d) : "l"(a), "l"(b));
    return d;
}
__device__ __forceinline__ ull pack2(float lo, float hi) {
    ull d;
    asm("mov.b64 %0, {%1, %2};" : "=l"(d) : "f"(lo), "f"(hi));
    return d;
}
__device__ __forceinline__ void unpack2(ull v, float& lo, float& hi) {
    asm("mov.b64 {%0, %1}, %2;" : "=f"(lo), "=f"(hi) : "l"(v));
}
__device__ __forceinline__ float fast_exp2(float x) {
    float y;
    asm("ex2.approx.ftz.f32 %0, %1;" : "=f"(y) : "f"(x));
    return y;
}

// ---------------------------------------------------------------------------
// Projection: [B*S, 256] @ [256, 64] x3 -> g_q, g_k, g_v  (unchanged; ~100us)
// ---------------------------------------------------------------------------
__global__ __launch_bounds__(192) void proj_kernel(
    const float* __restrict__ x,
    const float* __restrict__ wk,
    const float* __restrict__ wq,
    const float* __restrict__ wv)
{
    __shared__ __align__(16) float xs[32 * Ee];
    const int row0 = blockIdx.x * 32;
    const int t = threadIdx.x;

    const float4* xg = (const float4*)(x + (size_t)row0 * Ee);
    float4* xs4 = (float4*)xs;
    for (int i = t; i < 32 * (Ee / 4); i += 192) xs4[i] = xg[i];
    __syncthreads();

    const int h = t & 63;
    const float* W = (t < 64) ? wq : (t < 128) ? wk : wv;
    float* G = (t < 64) ? g_q : (t < 128) ? g_k : g_v;

    float acc[32];
#pragma unroll
    for (int r = 0; r < 32; r++) acc[r] = 0.f;

    for (int k = 0; k < Ee; k += 4) {
        float w0 = W[(k + 0) * Hh + h];
        float w1 = W[(k + 1) * Hh + h];
        float w2 = W[(k + 2) * Hh + h];
        float w3 = W[(k + 3) * Hh + h];
#pragma unroll
        for (int r = 0; r < 32; r++) {
            float4 xv = xs4[r * (Ee / 4) + (k >> 2)];
            acc[r] = fmaf(xv.x, w0, acc[r]);
            acc[r] = fmaf(xv.y, w1, acc[r]);
            acc[r] = fmaf(xv.z, w2, acc[r]);
            acc[r] = fmaf(xv.w, w3, acc[r]);
        }
    }
#pragma unroll
    for (int r = 0; r < 32; r++) G[(size_t)(row0 + r) * Hh + h] = acc[r];
}

// ---------------------------------------------------------------------------
// Flash attention, fp32, packed f32x2, SPLIT-H layout.
// Grid: (S/64, B) = (64, 4) = 256 blocks. Block: 128 threads.
// Thread t: query row = t>>1 (64 rows/block), half = t&1 (owns 32 of 64 dims).
// Halved registers -> ~140 regs -> 2 blocks/SM -> 8 warps/SM (2 per SMSP).
// Score = own half-dot + shfl.bfly(1); softmax stats bitwise-consistent
// across the lane pair. K/V 16x64 tiles double-buffered in smem.
// ---------------------------------------------------------------------------
#define KT 16

__global__ __launch_bounds__(128) void flash_kernel(float* __restrict__ out)
{
    __shared__ __align__(16) float sK[2][KT * Hh];
    __shared__ __align__(16) float sV[2][KT * Hh];

    const int b = blockIdx.y;
    const int t = threadIdx.x;
    const int row = t >> 1;          // 0..63
    const int half = t & 1;          // 0 or 1
    const int qrow = blockIdx.x * 64 + row;
    const int hoff = half * 32;      // dim offset this thread owns

    const float* qg = g_q + ((size_t)b * Ss + qrow) * Hh + hoff;
    const float4* kg4 = (const float4*)(g_k + (size_t)b * Ss * Hh);
    const float4* vg4 = (const float4*)(g_v + (size_t)b * Ss * Hh);

    // fold scale (n_emb^-0.5 = 1/16) and log2(e) into q
    const float qscale = 0.0625f * 1.4426950408889634f;

    ull q2[16];
#pragma unroll
    for (int i = 0; i < 8; i++) {
        float4 v = ((const float4*)qg)[i];
        q2[2 * i + 0] = pack2(v.x * qscale, v.y * qscale);
        q2[2 * i + 1] = pack2(v.z * qscale, v.w * qscale);
    }

    ull o2[16];
#pragma unroll
    for (int i = 0; i < 16; i++) o2[i] = 0ULL;

    float m = -1e30f;
    float l = 0.f;

    // preload tile 0: KT*Hh = 1024 floats = 256 float4; 2 per thread per tensor
    float4 rk0 = kg4[t];
    float4 rk1 = kg4[128 + t];
    float4 rv0 = vg4[t];
    float4 rv1 = vg4[128 + t];
    ((float4*)sK[0])[t] = rk0;
    ((float4*)sK[0])[128 + t] = rk1;
    ((float4*)sV[0])[t] = rv0;
    ((float4*)sV[0])[128 + t] = rv1;
    __syncthreads();

    const int NT = Ss / KT;  // 256
    for (int tile = 0; tile < NT; tile++) {
        const int cur = tile & 1;
        const int nxt = cur ^ 1;

        // prefetch next tile into registers (hidden under compute)
        if (tile + 1 < NT) {
            const float4* kn = kg4 + (tile + 1) * (KT * Hh / 4);
            const float4* vn = vg4 + (tile + 1) * (KT * Hh / 4);
            rk0 = kn[t];
            rk1 = kn[128 + t];
            rv0 = vn[t];
            rv1 = vn[128 + t];
        }

        // ---- half-scores: partial[j] = q_half . K[j]_half ----
        float sp[KT];
#pragma unroll 4
        for (int j = 0; j < KT; j++) {
            const ulonglong2* Kr = (const ulonglong2*)(sK[cur] + j * Hh + hoff);
            ull a0 = 0ULL, a1 = 0ULL;
#pragma unroll
            for (int d = 0; d < 8; d++) {
                ulonglong2 kk = Kr[d];
                a0 = ffma2(q2[2 * d + 0], kk.x, a0);
                a1 = ffma2(q2[2 * d + 1], kk.y, a1);
            }
            float x0, x1, y0, y1;
            unpack2(a0, x0, x1);
            unpack2(a1, y0, y1);
            sp[j] = (x0 + x1) + (y0 + y1);
        }

        // ---- combine halves (lane pair shares a query row) ----
        float s[KT];
#pragma unroll
        for (int j = 0; j < KT; j++)
            s[j] = sp[j] + __shfl_xor_sync(0xffffffffu, sp[j], 1);

        // ---- online softmax update (consistent across the pair) ----
        float mt = m;
#pragma unroll
        for (int j = 0; j < KT; j++) mt = fmaxf(mt, s[j]);
        float corr = fast_exp2(m - mt);
        m = mt;
        l *= corr;
        ull corr2 = pack2(corr, corr);
#pragma unroll
        for (int i = 0; i < 16; i++) o2[i] = fmul2(o2[i], corr2);

        // ---- accumulate P @ V (own half of dims) ----
#pragma unroll 4
        for (int j = 0; j < KT; j++) {
            float p = fast_exp2(s[j] - m);
            l += p;
            ull p2 = pack2(p, p);
            const ulonglong2* Vr = (const ulonglong2*)(sV[cur] + j * Hh + hoff);
#pragma unroll
            for (int d = 0; d < 8; d++) {
                ulonglong2 vv = Vr[d];
                o2[2 * d + 0] = ffma2(p2, vv.x, o2[2 * d + 0]);
                o2[2 * d + 1] = ffma2(p2, vv.y, o2[2 * d + 1]);
            }
        }

        // publish prefetched tile
        if (tile + 1 < NT) {
            ((float4*)sK[nxt])[t] = rk0;
            ((float4*)sK[nxt])[128 + t] = rk1;
            ((float4*)sV[nxt])[t] = rv0;
            ((float4*)sV[nxt])[128 + t] = rv1;
        }
        __syncthreads();
    }

    // ---- epilogue: O / l ----
    float inv = 1.f / l;
    float4* og = (float4*)(out + ((size_t)b * Ss + qrow) * Hh + hoff);
#pragma unroll
    for (int i = 0; i < 8; i++) {
        float x0, x1, y0, y1;
        unpack2(o2[2 * i + 0], x0, x1);
        unpack2(o2[2 * i + 1], y0, y1);
        float4 v;
        v.x = x0 * inv;
        v.y = x1 * inv;
        v.z = y0 * inv;
        v.w = y1 * inv;
        og[i] = v;
    }
}

extern "C" void kernel_launch(void* const* d_in, const int* in_sizes, int n_in,
                              void* d_out, int out_size)
{
    const float* ini_emb = (const float*)d_in[0];
    const float* wk = (const float*)d_in[1];
    const float* wq = (const float*)d_in[2];
    const float* wv = (const float*)d_in[3];
    float* out = (float*)d_out;

    proj_kernel<<<(Bb * Ss) / 32, 192>>>(ini_emb, wk, wq, wv);
    flash_kernel<<<dim3(Ss / 64, Bb), 128>>>(out);
}

// round 5
// speedup vs baseline: 5.2079x; 5.2079x over previous
#include <cuda_runtime.h>
#include <cstdint>

#define Bb 4
#define Ss 4096
#define Ee 256
#define Hh 64

// Scratch for projected Q, K, V (device globals: no allocation allowed)
__device__ float g_q[Bb * Ss * Hh];
__device__ float g_k[Bb * Ss * Hh];
__device__ float g_v[Bb * Ss * Hh];

__device__ __forceinline__ float fast_exp2(float x) {
    float y;
    asm("ex2.approx.ftz.f32 %0, %1;" : "=f"(y) : "f"(x));
    return y;
}
__device__ __forceinline__ float cvt_tf32(float x) {
    uint32_t u;
    asm("cvt.rna.tf32.f32 %0, %1;" : "=r"(u) : "f"(x));
    return __uint_as_float(u);
}
// D(16x8,f32) += A(16x8,tf32) @ B(8x8,tf32 col-major)
__device__ __forceinline__ void mma_tf32(float* d, const float* a, float b0, float b1) {
    asm("mma.sync.aligned.m16n8k8.row.col.f32.tf32.tf32.f32 "
        "{%0,%1,%2,%3}, {%4,%5,%6,%7}, {%8,%9}, {%0,%1,%2,%3};"
        : "+f"(d[0]), "+f"(d[1]), "+f"(d[2]), "+f"(d[3])
        : "r"(__float_as_uint(a[0])), "r"(__float_as_uint(a[1])),
          "r"(__float_as_uint(a[2])), "r"(__float_as_uint(a[3])),
          "r"(__float_as_uint(b0)), "r"(__float_as_uint(b1)));
}

// ---------------------------------------------------------------------------
// Projection: [B*S, 256] @ [256, 64] x3 -> g_q, g_k, g_v  (unchanged)
// ---------------------------------------------------------------------------
__global__ __launch_bounds__(192) void proj_kernel(
    const float* __restrict__ x,
    const float* __restrict__ wk,
    const float* __restrict__ wq,
    const float* __restrict__ wv)
{
    __shared__ __align__(16) float xs[32 * Ee];
    const int row0 = blockIdx.x * 32;
    const int t = threadIdx.x;

    const float4* xg = (const float4*)(x + (size_t)row0 * Ee);
    float4* xs4 = (float4*)xs;
    for (int i = t; i < 32 * (Ee / 4); i += 192) xs4[i] = xg[i];
    __syncthreads();

    const int h = t & 63;
    const float* W = (t < 64) ? wq : (t < 128) ? wk : wv;
    float* G = (t < 64) ? g_q : (t < 128) ? g_k : g_v;

    float acc[32];
#pragma unroll
    for (int r = 0; r < 32; r++) acc[r] = 0.f;

    for (int k = 0; k < Ee; k += 4) {
        float w0 = W[(k + 0) * Hh + h];
        float w1 = W[(k + 1) * Hh + h];
        float w2 = W[(k + 2) * Hh + h];
        float w3 = W[(k + 3) * Hh + h];
#pragma unroll
        for (int r = 0; r < 32; r++) {
            float4 xv = xs4[r * (Ee / 4) + (k >> 2)];
            acc[r] = fmaf(xv.x, w0, acc[r]);
            acc[r] = fmaf(xv.y, w1, acc[r]);
            acc[r] = fmaf(xv.z, w2, acc[r]);
            acc[r] = fmaf(xv.w, w3, acc[r]);
        }
    }
#pragma unroll
    for (int r = 0; r < 32; r++) G[(size_t)(row0 + r) * Hh + h] = acc[r];
}

// ---------------------------------------------------------------------------
// Flash attention via mma.sync tf32 (FA2 structure).
// Grid (S/64, B) = 256 blocks, 128 threads (4 warps x 16 query rows).
// K-tile Bc=32. K/V staged as tf32 in smem, double-buffered, with per-tensor
// padding chosen for conflict-free fragment loads (K pad 68, V pad 72).
// P goes through per-warp smem (pad 36) to re-fragment for the PV mma.
// ---------------------------------------------------------------------------
#define BC 32
#define PADK 68
#define PADV 72
#define PADP 36
#define NTILE (Ss / BC)   // 128

__global__ __launch_bounds__(128) void flash_kernel(float* __restrict__ out)
{
    __shared__ __align__(16) float sK[2][BC * PADK];
    __shared__ __align__(16) float sV[2][BC * PADV];
    __shared__ __align__(16) float sP[4][16 * PADP];

    const int b = blockIdx.y;
    const int t = threadIdx.x;
    const int warp = t >> 5;
    const int lane = t & 31;
    const int gid = lane >> 2;   // 0..7  (row group)
    const int tig = lane & 3;    // 0..3  (thread in group)
    const int row0 = blockIdx.x * 64 + warp * 16;

    const float* qg = g_q + ((size_t)b * Ss + row0) * Hh;
    const float4* kg4 = (const float4*)(g_k + (size_t)b * Ss * Hh);
    const float4* vg4 = (const float4*)(g_v + (size_t)b * Ss * Hh);

    // fold scale (n_emb^-0.5 = 1/16) and log2(e) into q
    const float qscale = 0.0625f * 1.4426950408889634f;

    // q fragments: 8 k-chunks x 4 regs (A of m16n8k8)
    float qa[8][4];
#pragma unroll
    for (int c = 0; c < 8; c++) {
        qa[c][0] = cvt_tf32(qg[(gid)     * Hh + c * 8 + tig    ] * qscale);
        qa[c][1] = cvt_tf32(qg[(gid + 8) * Hh + c * 8 + tig    ] * qscale);
        qa[c][2] = cvt_tf32(qg[(gid)     * Hh + c * 8 + tig + 4] * qscale);
        qa[c][3] = cvt_tf32(qg[(gid + 8) * Hh + c * 8 + tig + 4] * qscale);
    }

    // O accumulators: 8 n-tiles x 4 regs
    float o[8][4];
#pragma unroll
    for (int nt = 0; nt < 8; nt++)
#pragma unroll
        for (int j = 0; j < 4; j++) o[nt][j] = 0.f;

    float m0 = -1e30f, m1 = -1e30f;
    float l0 = 0.f, l1 = 0.f;

    // staging indices: thread handles float4 idx {t, t+128, t+256, t+384}
    // tile = BC*Hh = 2048 floats = 512 float4 per tensor
    float4 pk[4], pv[4];
#pragma unroll
    for (int i = 0; i < 4; i++) {
        pk[i] = kg4[t + i * 128];
        pv[i] = vg4[t + i * 128];
    }
    {
#pragma unroll
        for (int i = 0; i < 4; i++) {
            int idx = t + i * 128;
            int row = idx >> 4, c4 = idx & 15;
            float4 kv = pk[i];
            kv.x = cvt_tf32(kv.x); kv.y = cvt_tf32(kv.y);
            kv.z = cvt_tf32(kv.z); kv.w = cvt_tf32(kv.w);
            *(float4*)(&sK[0][row * PADK + c4 * 4]) = kv;
            float4 vv = pv[i];
            vv.x = cvt_tf32(vv.x); vv.y = cvt_tf32(vv.y);
            vv.z = cvt_tf32(vv.z); vv.w = cvt_tf32(vv.w);
            *(float4*)(&sV[0][row * PADV + c4 * 4]) = vv;
        }
    }
    __syncthreads();

    for (int tile = 0; tile < NTILE; tile++) {
        const int cur = tile & 1;
        const int nxt = cur ^ 1;

        // prefetch next tile into registers
        if (tile + 1 < NTILE) {
            const float4* kn = kg4 + (size_t)(tile + 1) * 512;
            const float4* vn = vg4 + (size_t)(tile + 1) * 512;
#pragma unroll
            for (int i = 0; i < 4; i++) {
                pk[i] = kn[t + i * 128];
                pv[i] = vn[t + i * 128];
            }
        }

        // ---- S = q @ K^T : 4 n-tiles (8 kpos each) x 8 k-chunks ----
        float s[4][4];
#pragma unroll
        for (int n = 0; n < 4; n++) {
            s[n][0] = s[n][1] = s[n][2] = s[n][3] = 0.f;
#pragma unroll
            for (int c = 0; c < 8; c++) {
                // B(col-major): b0 = K[n*8+gid][c*8+tig], b1 = +4 dims
                float b0 = sK[cur][(n * 8 + gid) * PADK + c * 8 + tig];
                float b1 = sK[cur][(n * 8 + gid) * PADK + c * 8 + tig + 4];
                mma_tf32(s[n], qa[c], b0, b1);
            }
        }

        // ---- online softmax (rows gid and gid+8; cols across quad) ----
        float rmax0 = s[0][0], rmax1 = s[0][2];
#pragma unroll
        for (int n = 0; n < 4; n++) {
            rmax0 = fmaxf(rmax0, fmaxf(s[n][0], s[n][1]));
            rmax1 = fmaxf(rmax1, fmaxf(s[n][2], s[n][3]));
        }
        rmax0 = fmaxf(rmax0, __shfl_xor_sync(0xffffffffu, rmax0, 1));
        rmax0 = fmaxf(rmax0, __shfl_xor_sync(0xffffffffu, rmax0, 2));
        rmax1 = fmaxf(rmax1, __shfl_xor_sync(0xffffffffu, rmax1, 1));
        rmax1 = fmaxf(rmax1, __shfl_xor_sync(0xffffffffu, rmax1, 2));

        float mn0 = fmaxf(m0, rmax0);
        float mn1 = fmaxf(m1, rmax1);
        float corr0 = fast_exp2(m0 - mn0);
        float corr1 = fast_exp2(m1 - mn1);
        m0 = mn0; m1 = mn1;
        l0 *= corr0; l1 *= corr1;
#pragma unroll
        for (int nt = 0; nt < 8; nt++) {
            o[nt][0] *= corr0; o[nt][1] *= corr0;
            o[nt][2] *= corr1; o[nt][3] *= corr1;
        }

        float p[4][4];
#pragma unroll
        for (int n = 0; n < 4; n++) {
            p[n][0] = fast_exp2(s[n][0] - m0);
            p[n][1] = fast_exp2(s[n][1] - m0);
            p[n][2] = fast_exp2(s[n][2] - m1);
            p[n][3] = fast_exp2(s[n][3] - m1);
            l0 += p[n][0] + p[n][1];
            l1 += p[n][2] + p[n][3];
        }

        // ---- stage P into per-warp smem (C-frag -> memory layout) ----
        __syncwarp();
#pragma unroll
        for (int n = 0; n < 4; n++) {
            float2 hi = make_float2(cvt_tf32(p[n][0]), cvt_tf32(p[n][1]));
            float2 lo = make_float2(cvt_tf32(p[n][2]), cvt_tf32(p[n][3]));
            *(float2*)(&sP[warp][(gid)     * PADP + n * 8 + 2 * tig]) = hi;
            *(float2*)(&sP[warp][(gid + 8) * PADP + n * 8 + 2 * tig]) = lo;
        }
        __syncwarp();

        // ---- O += P @ V : 4 k-chunks (8 kpos) x 8 n-tiles (8 dims) ----
#pragma unroll
        for (int kc = 0; kc < 4; kc++) {
            float a[4];
            a[0] = sP[warp][(gid)     * PADP + kc * 8 + tig    ];
            a[1] = sP[warp][(gid + 8) * PADP + kc * 8 + tig    ];
            a[2] = sP[warp][(gid)     * PADP + kc * 8 + tig + 4];
            a[3] = sP[warp][(gid + 8) * PADP + kc * 8 + tig + 4];
#pragma unroll
            for (int nt = 0; nt < 8; nt++) {
                // b0 = V[kc*8+tig][nt*8+gid], b1 = V[kc*8+tig+4][nt*8+gid]
                float b0 = sV[cur][(kc * 8 + tig)     * PADV + nt * 8 + gid];
                float b1 = sV[cur][(kc * 8 + tig + 4) * PADV + nt * 8 + gid];
                mma_tf32(o[nt], a, b0, b1);
            }
        }

        // ---- publish prefetched tile ----
        if (tile + 1 < NTILE) {
#pragma unroll
            for (int i = 0; i < 4; i++) {
                int idx = t + i * 128;
                int row = idx >> 4, c4 = idx & 15;
                float4 kv = pk[i];
                kv.x = cvt_tf32(kv.x); kv.y = cvt_tf32(kv.y);
                kv.z = cvt_tf32(kv.z); kv.w = cvt_tf32(kv.w);
                *(float4*)(&sK[nxt][row * PADK + c4 * 4]) = kv;
                float4 vv = pv[i];
                vv.x = cvt_tf32(vv.x); vv.y = cvt_tf32(vv.y);
                vv.z = cvt_tf32(vv.z); vv.w = cvt_tf32(vv.w);
                *(float4*)(&sV[nxt][row * PADV + c4 * 4]) = vv;
            }
        }
        __syncthreads();
    }

    // ---- epilogue: reduce l across quad, normalize, store ----
    l0 += __shfl_xor_sync(0xffffffffu, l0, 1);
    l0 += __shfl_xor_sync(0xffffffffu, l0, 2);
    l1 += __shfl_xor_sync(0xffffffffu, l1, 1);
    l1 += __shfl_xor_sync(0xffffffffu, l1, 2);
    float inv0 = 1.f / l0;
    float inv1 = 1.f / l1;

    float* outb = out + ((size_t)b * Ss + row0) * Hh;
#pragma unroll
    for (int nt = 0; nt < 8; nt++) {
        float2 r0 = make_float2(o[nt][0] * inv0, o[nt][1] * inv0);
        float2 r1 = make_float2(o[nt][2] * inv1, o[nt][3] * inv1);
        *(float2*)(&outb[(gid)     * Hh + nt * 8 + 2 * tig]) = r0;
        *(float2*)(&outb[(gid + 8) * Hh + nt * 8 + 2 * tig]) = r1;
    }
}

extern "C" void kernel_launch(void* const* d_in, const int* in_sizes, int n_in,
                              void* d_out, int out_size)
{
    const float* ini_emb = (const float*)d_in[0];
    const float* wk = (const float*)d_in[1];
    const float* wq = (const float*)d_in[2];
    const float* wv = (const float*)d_in[3];
    float* out = (float*)d_out;

    proj_kernel<<<(Bb * Ss) / 32, 192>>>(ini_emb, wk, wq, wv);
    flash_kernel<<<dim3(Ss / 64, Bb), 128>>>(out);
}

// round 6
// speedup vs baseline: 5.6097x; 1.0771x over previous
#include <cuda_runtime.h>
#include <cstdint>

#define Bb 4
#define Ss 4096
#define Ee 256
#define Hh 64
#define RTOT (Bb * Ss)

#define SPLITS 4
#define SKEY (Ss / SPLITS)   // 1024 keys per split

// Scratch (device globals: no allocation allowed)
__device__ float g_q[RTOT * Hh];
__device__ float g_k[RTOT * Hh];
__device__ float g_v[RTOT * Hh];
__device__ float g_po[SPLITS * RTOT * Hh];   // unnormalized partial O
__device__ float g_pm[SPLITS * RTOT];        // partial row max (log2 domain)
__device__ float g_pl[SPLITS * RTOT];        // partial row sum

typedef unsigned long long ull;

__device__ __forceinline__ float fast_exp2(float x) {
    float y;
    asm("ex2.approx.ftz.f32 %0, %1;" : "=f"(y) : "f"(x));
    return y;
}
__device__ __forceinline__ float cvt_tf32(float x) {
    uint32_t u;
    asm("cvt.rna.tf32.f32 %0, %1;" : "=r"(u) : "f"(x));
    return __uint_as_float(u);
}
__device__ __forceinline__ ull ffma2(ull a, ull b, ull c) {
    ull d;
    asm("fma.rn.f32x2 %0, %1, %2, %3;" : "=l"(d) : "l"(a), "l"(b), "l"(c));
    return d;
}
__device__ __forceinline__ ull pack2(float lo, float hi) {
    ull d;
    asm("mov.b64 %0, {%1, %2};" : "=l"(d) : "f"(lo), "f"(hi));
    return d;
}
__device__ __forceinline__ void unpack2(ull v, float& lo, float& hi) {
    asm("mov.b64 {%0, %1}, %2;" : "=f"(lo), "=f"(hi) : "l"(v));
}
// D(16x8,f32) += A(16x8,tf32) @ B(8x8,tf32 col-major)
__device__ __forceinline__ void mma_tf32(float* d, const float* a, float b0, float b1) {
    asm("mma.sync.aligned.m16n8k8.row.col.f32.tf32.tf32.f32 "
        "{%0,%1,%2,%3}, {%4,%5,%6,%7}, {%8,%9}, {%0,%1,%2,%3};"
        : "+f"(d[0]), "+f"(d[1]), "+f"(d[2]), "+f"(d[3])
        : "r"(__float_as_uint(a[0])), "r"(__float_as_uint(a[1])),
          "r"(__float_as_uint(a[2])), "r"(__float_as_uint(a[3])),
          "r"(__float_as_uint(b0)), "r"(__float_as_uint(b1)));
}

// ---------------------------------------------------------------------------
// Projection with packed f32x2 FMA. x staged TRANSPOSED in smem (xs_t[k][row],
// stride 36 floats -> 16B aligned rows) so adjacent rows form f32x2 pairs and
// one LDS.128 feeds two ffma2. Thread t owns one output column of Q|K|V.
// ---------------------------------------------------------------------------
#define XPAD 36

__global__ __launch_bounds__(192) void proj_kernel(
    const float* __restrict__ x,
    const float* __restrict__ wk,
    const float* __restrict__ wq,
    const float* __restrict__ wv)
{
    __shared__ __align__(16) float xs_t[Ee * XPAD];  // 36 KB
    const int row0 = blockIdx.x * 32;
    const int t = threadIdx.x;

    // stage transposed: read coalesced float4 (row, 4k..), scatter 4 STS
    const float4* xg = (const float4*)(x + (size_t)row0 * Ee);
    for (int i = t; i < 32 * (Ee / 4); i += 192) {
        int row = i >> 6;        // 0..31
        int kq = i & 63;         // float4 index within row
        float4 v = xg[i];
        xs_t[(4 * kq + 0) * XPAD + row] = v.x;
        xs_t[(4 * kq + 1) * XPAD + row] = v.y;
        xs_t[(4 * kq + 2) * XPAD + row] = v.z;
        xs_t[(4 * kq + 3) * XPAD + row] = v.w;
    }
    __syncthreads();

    const int h = t & 63;
    const float* W = (t < 64) ? wq : (t < 128) ? wk : wv;
    float* G = (t < 64) ? g_q : (t < 128) ? g_k : g_v;

    ull acc2[16];
#pragma unroll
    for (int i = 0; i < 16; i++) acc2[i] = 0ULL;

#pragma unroll 4
    for (int k = 0; k < Ee; k++) {
        float w = W[k * Hh + h];
        ull w2 = pack2(w, w);
        const ulonglong2* xp = (const ulonglong2*)&xs_t[k * XPAD];
#pragma unroll
        for (int j = 0; j < 8; j++) {
            ulonglong2 x2 = xp[j];           // rows 4j..4j+3 (broadcast)
            acc2[2 * j + 0] = ffma2(x2.x, w2, acc2[2 * j + 0]);
            acc2[2 * j + 1] = ffma2(x2.y, w2, acc2[2 * j + 1]);
        }
    }

#pragma unroll
    for (int i = 0; i < 16; i++) {
        float a, bv;
        unpack2(acc2[i], a, bv);
        G[(size_t)(row0 + 2 * i + 0) * Hh + h] = a;
        G[(size_t)(row0 + 2 * i + 1) * Hh + h] = bv;
    }
}

// ---------------------------------------------------------------------------
// Flash attention via mma.sync tf32, SPLIT-KV x4.
// Grid (S/64, B, SPLITS) = 1024 blocks, 128 threads (4 warps x 16 q rows).
// Each block covers SKEY=1024 keys, writes unnormalized partial (O, m, l).
// ---------------------------------------------------------------------------
#define BC 32
#define PADK 68
#define PADV 72
#define PADP 36
#define NTILE (SKEY / BC)   // 32

__global__ __launch_bounds__(128) void flash_kernel()
{
    __shared__ __align__(16) float sK[2][BC * PADK];
    __shared__ __align__(16) float sV[2][BC * PADV];
    __shared__ __align__(16) float sP[4][16 * PADP];

    const int b = blockIdx.y;
    const int split = blockIdx.z;
    const int t = threadIdx.x;
    const int warp = t >> 5;
    const int lane = t & 31;
    const int gid = lane >> 2;
    const int tig = lane & 3;
    const int row0 = blockIdx.x * 64 + warp * 16;

    const float* qg = g_q + ((size_t)b * Ss + row0) * Hh;
    const float4* kg4 = (const float4*)(g_k + ((size_t)b * Ss + split * SKEY) * Hh);
    const float4* vg4 = (const float4*)(g_v + ((size_t)b * Ss + split * SKEY) * Hh);

    const float qscale = 0.0625f * 1.4426950408889634f;

    float qa[8][4];
#pragma unroll
    for (int c = 0; c < 8; c++) {
        qa[c][0] = cvt_tf32(qg[(gid)     * Hh + c * 8 + tig    ] * qscale);
        qa[c][1] = cvt_tf32(qg[(gid + 8) * Hh + c * 8 + tig    ] * qscale);
        qa[c][2] = cvt_tf32(qg[(gid)     * Hh + c * 8 + tig + 4] * qscale);
        qa[c][3] = cvt_tf32(qg[(gid + 8) * Hh + c * 8 + tig + 4] * qscale);
    }

    float o[8][4];
#pragma unroll
    for (int nt = 0; nt < 8; nt++)
#pragma unroll
        for (int j = 0; j < 4; j++) o[nt][j] = 0.f;

    float m0 = -1e30f, m1 = -1e30f;
    float l0 = 0.f, l1 = 0.f;

    float4 pk[4], pv[4];
#pragma unroll
    for (int i = 0; i < 4; i++) {
        pk[i] = kg4[t + i * 128];
        pv[i] = vg4[t + i * 128];
    }
#pragma unroll
    for (int i = 0; i < 4; i++) {
        int idx = t + i * 128;
        int row = idx >> 4, c4 = idx & 15;
        float4 kv = pk[i];
        kv.x = cvt_tf32(kv.x); kv.y = cvt_tf32(kv.y);
        kv.z = cvt_tf32(kv.z); kv.w = cvt_tf32(kv.w);
        *(float4*)(&sK[0][row * PADK + c4 * 4]) = kv;
        float4 vv = pv[i];
        vv.x = cvt_tf32(vv.x); vv.y = cvt_tf32(vv.y);
        vv.z = cvt_tf32(vv.z); vv.w = cvt_tf32(vv.w);
        *(float4*)(&sV[0][row * PADV + c4 * 4]) = vv;
    }
    __syncthreads();

    for (int tile = 0; tile < NTILE; tile++) {
        const int cur = tile & 1;
        const int nxt = cur ^ 1;

        if (tile + 1 < NTILE) {
            const float4* kn = kg4 + (size_t)(tile + 1) * 512;
            const float4* vn = vg4 + (size_t)(tile + 1) * 512;
#pragma unroll
            for (int i = 0; i < 4; i++) {
                pk[i] = kn[t + i * 128];
                pv[i] = vn[t + i * 128];
            }
        }

        // ---- S = q @ K^T ----
        float s[4][4];
#pragma unroll
        for (int n = 0; n < 4; n++) {
            s[n][0] = s[n][1] = s[n][2] = s[n][3] = 0.f;
#pragma unroll
            for (int c = 0; c < 8; c++) {
                float b0 = sK[cur][(n * 8 + gid) * PADK + c * 8 + tig];
                float b1 = sK[cur][(n * 8 + gid) * PADK + c * 8 + tig + 4];
                mma_tf32(s[n], qa[c], b0, b1);
            }
        }

        // ---- online softmax ----
        float rmax0 = s[0][0], rmax1 = s[0][2];
#pragma unroll
        for (int n = 0; n < 4; n++) {
            rmax0 = fmaxf(rmax0, fmaxf(s[n][0], s[n][1]));
            rmax1 = fmaxf(rmax1, fmaxf(s[n][2], s[n][3]));
        }
        rmax0 = fmaxf(rmax0, __shfl_xor_sync(0xffffffffu, rmax0, 1));
        rmax0 = fmaxf(rmax0, __shfl_xor_sync(0xffffffffu, rmax0, 2));
        rmax1 = fmaxf(rmax1, __shfl_xor_sync(0xffffffffu, rmax1, 1));
        rmax1 = fmaxf(rmax1, __shfl_xor_sync(0xffffffffu, rmax1, 2));

        float mn0 = fmaxf(m0, rmax0);
        float mn1 = fmaxf(m1, rmax1);
        float corr0 = fast_exp2(m0 - mn0);
        float corr1 = fast_exp2(m1 - mn1);
        m0 = mn0; m1 = mn1;
        l0 *= corr0; l1 *= corr1;
#pragma unroll
        for (int nt = 0; nt < 8; nt++) {
            o[nt][0] *= corr0; o[nt][1] *= corr0;
            o[nt][2] *= corr1; o[nt][3] *= corr1;
        }

        float p[4][4];
#pragma unroll
        for (int n = 0; n < 4; n++) {
            p[n][0] = fast_exp2(s[n][0] - m0);
            p[n][1] = fast_exp2(s[n][1] - m0);
            p[n][2] = fast_exp2(s[n][2] - m1);
            p[n][3] = fast_exp2(s[n][3] - m1);
            l0 += p[n][0] + p[n][1];
            l1 += p[n][2] + p[n][3];
        }

        // ---- stage P (C-frag -> memory layout) ----
        __syncwarp();
#pragma unroll
        for (int n = 0; n < 4; n++) {
            float2 hi = make_float2(cvt_tf32(p[n][0]), cvt_tf32(p[n][1]));
            float2 lo = make_float2(cvt_tf32(p[n][2]), cvt_tf32(p[n][3]));
            *(float2*)(&sP[warp][(gid)     * PADP + n * 8 + 2 * tig]) = hi;
            *(float2*)(&sP[warp][(gid + 8) * PADP + n * 8 + 2 * tig]) = lo;
        }
        __syncwarp();

        // ---- O += P @ V ----
#pragma unroll
        for (int kc = 0; kc < 4; kc++) {
            float a[4];
            a[0] = sP[warp][(gid)     * PADP + kc * 8 + tig    ];
            a[1] = sP[warp][(gid + 8) * PADP + kc * 8 + tig    ];
            a[2] = sP[warp][(gid)     * PADP + kc * 8 + tig + 4];
            a[3] = sP[warp][(gid + 8) * PADP + kc * 8 + tig + 4];
#pragma unroll
            for (int nt = 0; nt < 8; nt++) {
                float b0 = sV[cur][(kc * 8 + tig)     * PADV + nt * 8 + gid];
                float b1 = sV[cur][(kc * 8 + tig + 4) * PADV + nt * 8 + gid];
                mma_tf32(o[nt], a, b0, b1);
            }
        }

        if (tile + 1 < NTILE) {
#pragma unroll
            for (int i = 0; i < 4; i++) {
                int idx = t + i * 128;
                int row = idx >> 4, c4 = idx & 15;
                float4 kv = pk[i];
                kv.x = cvt_tf32(kv.x); kv.y = cvt_tf32(kv.y);
                kv.z = cvt_tf32(kv.z); kv.w = cvt_tf32(kv.w);
                *(float4*)(&sK[nxt][row * PADK + c4 * 4]) = kv;
                float4 vv = pv[i];
                vv.x = cvt_tf32(vv.x); vv.y = cvt_tf32(vv.y);
                vv.z = cvt_tf32(vv.z); vv.w = cvt_tf32(vv.w);
                *(float4*)(&sV[nxt][row * PADV + c4 * 4]) = vv;
            }
        }
        __syncthreads();
    }

    // ---- epilogue: reduce l across quad; write unnormalized partials ----
    l0 += __shfl_xor_sync(0xffffffffu, l0, 1);
    l0 += __shfl_xor_sync(0xffffffffu, l0, 2);
    l1 += __shfl_xor_sync(0xffffffffu, l1, 1);
    l1 += __shfl_xor_sync(0xffffffffu, l1, 2);

    float* po = g_po + ((size_t)split * RTOT + (size_t)b * Ss + row0) * Hh;
#pragma unroll
    for (int nt = 0; nt < 8; nt++) {
        *(float2*)(&po[(gid)     * Hh + nt * 8 + 2 * tig]) = make_float2(o[nt][0], o[nt][1]);
        *(float2*)(&po[(gid + 8) * Hh + nt * 8 + 2 * tig]) = make_float2(o[nt][2], o[nt][3]);
    }
    if (tig == 0) {
        size_t rbase = (size_t)split * RTOT + (size_t)b * Ss + row0;
        g_pm[rbase + gid] = m0;
        g_pm[rbase + gid + 8] = m1;
        g_pl[rbase + gid] = l0;
        g_pl[rbase + gid + 8] = l1;
    }
}

// ---------------------------------------------------------------------------
// Combine: merge SPLITS partials per row. Thread = (row, 16-dim quarter).
// ---------------------------------------------------------------------------
__global__ __launch_bounds__(256) void combine_kernel(float* __restrict__ out)
{
    const int idx = blockIdx.x * 256 + threadIdx.x;   // 0 .. RTOT*4-1
    const int row = idx >> 2;
    const int q = idx & 3;

    float m[SPLITS], l[SPLITS];
#pragma unroll
    for (int s = 0; s < SPLITS; s++) {
        m[s] = g_pm[(size_t)s * RTOT + row];
        l[s] = g_pl[(size_t)s * RTOT + row];
    }
    float M = m[0];
#pragma unroll
    for (int s = 1; s < SPLITS; s++) M = fmaxf(M, m[s]);
    float L = 0.f;
#pragma unroll
    for (int s = 0; s < SPLITS; s++) L += l[s] * fast_exp2(m[s] - M);
    float inv = 1.f / L;

    float4 acc[4];
#pragma unroll
    for (int i = 0; i < 4; i++) acc[i] = make_float4(0.f, 0.f, 0.f, 0.f);
#pragma unroll
    for (int s = 0; s < SPLITS; s++) {
        float w = fast_exp2(m[s] - M) * inv;
        const float4* p = (const float4*)(g_po + ((size_t)s * RTOT + row) * Hh + q * 16);
#pragma unroll
        for (int i = 0; i < 4; i++) {
            float4 v = p[i];
            acc[i].x += v.x * w;
            acc[i].y += v.y * w;
            acc[i].z += v.z * w;
            acc[i].w += v.w * w;
        }
    }
    float4* og = (float4*)(out + (size_t)row * Hh + q * 16);
#pragma unroll
    for (int i = 0; i < 4; i++) og[i] = acc[i];
}

extern "C" void kernel_launch(void* const* d_in, const int* in_sizes, int n_in,
                              void* d_out, int out_size)
{
    const float* ini_emb = (const float*)d_in[0];
    const float* wk = (const float*)d_in[1];
    const float* wq = (const float*)d_in[2];
    const float* wv = (const float*)d_in[3];
    float* out = (float*)d_out;

    proj_kernel<<<(Bb * Ss) / 32, 192>>>(ini_emb, wk, wq, wv);
    flash_kernel<<<dim3(Ss / 64, Bb, SPLITS), 128>>>();
    combine_kernel<<<(RTOT * 4) / 256, 256>>>(out);
}

// round 8
// speedup vs baseline: 7.0848x; 1.2629x over previous
#include <cuda_runtime.h>
#include <cstdint>

#define Bb 4
#define Ss 4096
#define Ee 256
#define Hh 64
#define RTOT (Bb * Ss)

#define SPLITS 4
#define SKEY (Ss / SPLITS)   // 1024 keys per split

// Scratch (device globals: no allocation allowed)
__device__ float g_q[RTOT * Hh];
__device__ float g_k[RTOT * Hh];
__device__ float g_v[RTOT * Hh];
__device__ float g_po[SPLITS * RTOT * Hh];   // unnormalized partial O
__device__ float g_pm[SPLITS * RTOT];        // partial row max (log2 domain)
__device__ float g_pl[SPLITS * RTOT];        // partial row sum

__device__ __forceinline__ float fast_exp2(float x) {
    float y;
    asm("ex2.approx.ftz.f32 %0, %1;" : "=f"(y) : "f"(x));
    return y;
}
__device__ __forceinline__ float cvt_tf32(float x) {
    uint32_t u;
    asm("cvt.rna.tf32.f32 %0, %1;" : "=r"(u) : "f"(x));
    return __uint_as_float(u);
}
__device__ __forceinline__ float4 cvt4(float4 v) {
    v.x = cvt_tf32(v.x); v.y = cvt_tf32(v.y);
    v.z = cvt_tf32(v.z); v.w = cvt_tf32(v.w);
    return v;
}
// D(16x8,f32) += A(16x8,tf32) @ B(8x8,tf32 col-major)
__device__ __forceinline__ void mma_tf32(float* d, const float* a, float b0, float b1) {
    asm("mma.sync.aligned.m16n8k8.row.col.f32.tf32.tf32.f32 "
        "{%0,%1,%2,%3}, {%4,%5,%6,%7}, {%8,%9}, {%0,%1,%2,%3};"
        : "+f"(d[0]), "+f"(d[1]), "+f"(d[2]), "+f"(d[3])
        : "r"(__float_as_uint(a[0])), "r"(__float_as_uint(a[1])),
          "r"(__float_as_uint(a[2])), "r"(__float_as_uint(a[3])),
          "r"(__float_as_uint(b0)), "r"(__float_as_uint(b1)));
}
// same, but RNA-round the B operands first (smem holds raw fp32)
__device__ __forceinline__ void mma_tf32_cvtB(float* d, const float* a, float b0, float b1) {
    mma_tf32(d, a, cvt_tf32(b0), cvt_tf32(b1));
}
__device__ __forceinline__ void cp16(uint32_t dst, const void* src) {
    asm volatile("cp.async.ca.shared.global [%0], [%1], 16;" :: "r"(dst), "l"(src));
}
__device__ __forceinline__ void cp_commit() {
    asm volatile("cp.async.commit_group;" ::: "memory");
}
__device__ __forceinline__ void cp_wait0() {
    asm volatile("cp.async.wait_group 0;" ::: "memory");
}

// ---------------------------------------------------------------------------
// Projection via tf32 mma: [B*S,256] @ [256,192] -> g_q|g_k|g_v.
// 512 blocks x 128 thr. Block: 32 rows x 192 cols. Warp w: row-group (w&1),
// col-half (w>>1) -> 16 rows x 96 cols = 12 n-tiles. 8 k-passes of 32.
// sX [32][36], sW [3][32][72]; operands RNA-rounded at staging time.
// ---------------------------------------------------------------------------
#define XP 36
#define WP 72

__global__ __launch_bounds__(128) void proj_kernel(
    const float* __restrict__ x,
    const float* __restrict__ wk,
    const float* __restrict__ wq,
    const float* __restrict__ wv)
{
    __shared__ __align__(16) float sX[32 * XP];        // 4.6 KB
    __shared__ __align__(16) float sW[3 * 32 * WP];    // 27.6 KB
    const int row0 = blockIdx.x * 32;
    const int t = threadIdx.x;
    const int warp = t >> 5;
    const int lane = t & 31;
    const int gid = lane >> 2;
    const int tig = lane & 3;
    const int mg = warp & 1;         // row-group
    const int ch = warp >> 1;        // col-half

    const float4* xg4 = (const float4*)x;
    const float4* w4[3] = {(const float4*)wq, (const float4*)wk, (const float4*)wv};

    // per-warp n-tile -> sW base offsets
    int sWoff[12];
#pragma unroll
    for (int nt = 0; nt < 12; nt++) {
        int gcol = ch * 96 + nt * 8;
        sWoff[nt] = (gcol >> 6) * (32 * WP) + (gcol & 63) + gid;
    }

    float o[12][4];
#pragma unroll
    for (int nt = 0; nt < 12; nt++)
#pragma unroll
        for (int j = 0; j < 4; j++) o[nt][j] = 0.f;

    for (int kp = 0; kp < 8; kp++) {
        const int k0q = kp * 8;   // float4 offset in k

        // stage x chunk (RNA): 32 rows x 32 k = 256 float4
#pragma unroll
        for (int i = 0; i < 2; i++) {
            int idx = t + i * 128;
            int row = idx >> 3, kq = idx & 7;
            float4 v = cvt4(xg4[(size_t)(row0 + row) * 64 + k0q + kq]);
            *(float4*)(&sX[row * XP + kq * 4]) = v;
        }
        // stage W chunk (RNA): 3 x 32k x 64 = 1536 float4
#pragma unroll
        for (int i = 0; i < 12; i++) {
            int idx = t + i * 128;
            int m = idx >> 9, rem = idx & 511;
            int k = rem >> 4, cq = rem & 15;
            float4 v = cvt4(w4[m][(size_t)(kp * 32 + k) * 16 + cq]);
            *(float4*)(&sW[m * (32 * WP) + k * WP + cq * 4]) = v;
        }
        __syncthreads();

#pragma unroll
        for (int c = 0; c < 4; c++) {
            float a[4];
            a[0] = sX[(mg * 16 + gid)     * XP + c * 8 + tig];
            a[1] = sX[(mg * 16 + gid + 8) * XP + c * 8 + tig];
            a[2] = sX[(mg * 16 + gid)     * XP + c * 8 + tig + 4];
            a[3] = sX[(mg * 16 + gid + 8) * XP + c * 8 + tig + 4];
#pragma unroll
            for (int nt = 0; nt < 12; nt++) {
                float b0 = sW[sWoff[nt] + (c * 8 + tig)     * WP];
                float b1 = sW[sWoff[nt] + (c * 8 + tig + 4) * WP];
                mma_tf32(o[nt], a, b0, b1);
            }
        }
        __syncthreads();
    }

    // epilogue: C frag -> g_q|g_k|g_v
    const int r = row0 + mg * 16 + gid;
#pragma unroll
    for (int nt = 0; nt < 12; nt++) {
        int gcol = ch * 96 + nt * 8;
        float* G = (gcol < 64) ? g_q : (gcol < 128) ? g_k : g_v;
        int lcol = (gcol & 63) + 2 * tig;
        *(float2*)(&G[(size_t)r * Hh + lcol])       = make_float2(o[nt][0], o[nt][1]);
        *(float2*)(&G[(size_t)(r + 8) * Hh + lcol]) = make_float2(o[nt][2], o[nt][3]);
    }
}

// ---------------------------------------------------------------------------
// Flash attention via mma.sync tf32, SPLIT-KV x4, cp.async K/V staging.
// Grid (S/64, B, SPLITS) = 1024 blocks, 128 threads (4 warps x 16 q rows).
// K/V land in smem as raw fp32; B-fragments RNA-rounded in registers.
// ---------------------------------------------------------------------------
#define BC 32
#define PADK 68
#define PADV 72
#define PADP 36
#define NTILE (SKEY / BC)   // 32
#define KBUFB (BC * PADK * 4)
#define VBUFB (BC * PADV * 4)

__global__ __launch_bounds__(128, 4) void flash_kernel()
{
    __shared__ __align__(16) float sK[2][BC * PADK];
    __shared__ __align__(16) float sV[2][BC * PADV];
    __shared__ __align__(16) float sP[4][16 * PADP];

    const int b = blockIdx.y;
    const int split = blockIdx.z;
    const int t = threadIdx.x;
    const int warp = t >> 5;
    const int lane = t & 31;
    const int gid = lane >> 2;
    const int tig = lane & 3;
    const int row0 = blockIdx.x * 64 + warp * 16;

    const float* qg = g_q + ((size_t)b * Ss + row0) * Hh;
    const float4* kg4 = (const float4*)(g_k + ((size_t)b * Ss + split * SKEY) * Hh);
    const float4* vg4 = (const float4*)(g_v + ((size_t)b * Ss + split * SKEY) * Hh);

    const uint32_t skb = (uint32_t)__cvta_generic_to_shared(&sK[0][0]);
    const uint32_t svb = (uint32_t)__cvta_generic_to_shared(&sV[0][0]);

    const float qscale = 0.0625f * 1.4426950408889634f;

    float qa[8][4];
#pragma unroll
    for (int c = 0; c < 8; c++) {
        qa[c][0] = cvt_tf32(qg[(gid)     * Hh + c * 8 + tig    ] * qscale);
        qa[c][1] = cvt_tf32(qg[(gid + 8) * Hh + c * 8 + tig    ] * qscale);
        qa[c][2] = cvt_tf32(qg[(gid)     * Hh + c * 8 + tig + 4] * qscale);
        qa[c][3] = cvt_tf32(qg[(gid + 8) * Hh + c * 8 + tig + 4] * qscale);
    }

    float o[8][4];
#pragma unroll
    for (int nt = 0; nt < 8; nt++)
#pragma unroll
        for (int j = 0; j < 4; j++) o[nt][j] = 0.f;

    float m0 = -1e30f, m1 = -1e30f;
    float l0 = 0.f, l1 = 0.f;

    // async-stage tile 0 into buffer 0
#pragma unroll
    for (int i = 0; i < 4; i++) {
        int idx = t + i * 128;
        int row = idx >> 4, c4 = idx & 15;
        cp16(skb + (uint32_t)(row * PADK + c4 * 4) * 4, kg4 + idx);
        cp16(svb + (uint32_t)(row * PADV + c4 * 4) * 4, vg4 + idx);
    }
    cp_commit();
    cp_wait0();
    __syncthreads();

    for (int tile = 0; tile < NTILE; tile++) {
        const int cur = tile & 1;
        const int nxt = cur ^ 1;

        // async prefetch next tile into the other buffer
        if (tile + 1 < NTILE) {
            const float4* kn = kg4 + (size_t)(tile + 1) * 512;
            const float4* vn = vg4 + (size_t)(tile + 1) * 512;
#pragma unroll
            for (int i = 0; i < 4; i++) {
                int idx = t + i * 128;
                int row = idx >> 4, c4 = idx & 15;
                cp16(skb + nxt * KBUFB + (uint32_t)(row * PADK + c4 * 4) * 4, kn + idx);
                cp16(svb + nxt * VBUFB + (uint32_t)(row * PADV + c4 * 4) * 4, vn + idx);
            }
            cp_commit();
        }

        // ---- S = q @ K^T (B-frags RNA-rounded in regs) ----
        float s[4][4];
#pragma unroll
        for (int n = 0; n < 4; n++) {
            s[n][0] = s[n][1] = s[n][2] = s[n][3] = 0.f;
#pragma unroll
            for (int c = 0; c < 8; c++) {
                float b0 = sK[cur][(n * 8 + gid) * PADK + c * 8 + tig];
                float b1 = sK[cur][(n * 8 + gid) * PADK + c * 8 + tig + 4];
                mma_tf32_cvtB(s[n], qa[c], b0, b1);
            }
        }

        // ---- online softmax ----
        float rmax0 = s[0][0], rmax1 = s[0][2];
#pragma unroll
        for (int n = 0; n < 4; n++) {
            rmax0 = fmaxf(rmax0, fmaxf(s[n][0], s[n][1]));
            rmax1 = fmaxf(rmax1, fmaxf(s[n][2], s[n][3]));
        }
        rmax0 = fmaxf(rmax0, __shfl_xor_sync(0xffffffffu, rmax0, 1));
        rmax0 = fmaxf(rmax0, __shfl_xor_sync(0xffffffffu, rmax0, 2));
        rmax1 = fmaxf(rmax1, __shfl_xor_sync(0xffffffffu, rmax1, 1));
        rmax1 = fmaxf(rmax1, __shfl_xor_sync(0xffffffffu, rmax1, 2));

        float mn0 = fmaxf(m0, rmax0);
        float mn1 = fmaxf(m1, rmax1);
        float corr0 = fast_exp2(m0 - mn0);
        float corr1 = fast_exp2(m1 - mn1);
        m0 = mn0; m1 = mn1;
        l0 *= corr0; l1 *= corr1;
#pragma unroll
        for (int nt = 0; nt < 8; nt++) {
            o[nt][0] *= corr0; o[nt][1] *= corr0;
            o[nt][2] *= corr1; o[nt][3] *= corr1;
        }

        float p[4][4];
#pragma unroll
        for (int n = 0; n < 4; n++) {
            p[n][0] = fast_exp2(s[n][0] - m0);
            p[n][1] = fast_exp2(s[n][1] - m0);
            p[n][2] = fast_exp2(s[n][2] - m1);
            p[n][3] = fast_exp2(s[n][3] - m1);
            l0 += p[n][0] + p[n][1];
            l1 += p[n][2] + p[n][3];
        }

        // ---- stage P (RNA; C-frag -> memory layout) ----
        __syncwarp();
#pragma unroll
        for (int n = 0; n < 4; n++) {
            float2 hi = make_float2(cvt_tf32(p[n][0]), cvt_tf32(p[n][1]));
            float2 lo = make_float2(cvt_tf32(p[n][2]), cvt_tf32(p[n][3]));
            *(float2*)(&sP[warp][(gid)     * PADP + n * 8 + 2 * tig]) = hi;
            *(float2*)(&sP[warp][(gid + 8) * PADP + n * 8 + 2 * tig]) = lo;
        }
        __syncwarp();

        // ---- O += P @ V (B-frags RNA-rounded in regs) ----
#pragma unroll
        for (int kc = 0; kc < 4; kc++) {
            float a[4];
            a[0] = sP[warp][(gid)     * PADP + kc * 8 + tig    ];
            a[1] = sP[warp][(gid + 8) * PADP + kc * 8 + tig    ];
            a[2] = sP[warp][(gid)     * PADP + kc * 8 + tig + 4];
            a[3] = sP[warp][(gid + 8) * PADP + kc * 8 + tig + 4];
#pragma unroll
            for (int nt = 0; nt < 8; nt++) {
                float b0 = sV[cur][(kc * 8 + tig)     * PADV + nt * 8 + gid];
                float b1 = sV[cur][(kc * 8 + tig + 4) * PADV + nt * 8 + gid];
                mma_tf32_cvtB(o[nt], a, b0, b1);
            }
        }

        cp_wait0();
        __syncthreads();
    }

    // ---- epilogue: reduce l across quad; write unnormalized partials ----
    l0 += __shfl_xor_sync(0xffffffffu, l0, 1);
    l0 += __shfl_xor_sync(0xffffffffu, l0, 2);
    l1 += __shfl_xor_sync(0xffffffffu, l1, 1);
    l1 += __shfl_xor_sync(0xffffffffu, l1, 2);

    float* po = g_po + ((size_t)split * RTOT + (size_t)b * Ss + row0) * Hh;
#pragma unroll
    for (int nt = 0; nt < 8; nt++) {
        *(float2*)(&po[(gid)     * Hh + nt * 8 + 2 * tig]) = make_float2(o[nt][0], o[nt][1]);
        *(float2*)(&po[(gid + 8) * Hh + nt * 8 + 2 * tig]) = make_float2(o[nt][2], o[nt][3]);
    }
    if (tig == 0) {
        size_t rbase = (size_t)split * RTOT + (size_t)b * Ss + row0;
        g_pm[rbase + gid] = m0;
        g_pm[rbase + gid + 8] = m1;
        g_pl[rbase + gid] = l0;
        g_pl[rbase + gid + 8] = l1;
    }
}

// ---------------------------------------------------------------------------
// Combine: merge SPLITS partials per row. Thread = (row, 16-dim quarter).
// ---------------------------------------------------------------------------
__global__ __launch_bounds__(256) void combine_kernel(float* __restrict__ out)
{
    const int idx = blockIdx.x * 256 + threadIdx.x;
    const int row = idx >> 2;
    const int q = idx & 3;

    float m[SPLITS], l[SPLITS];
#pragma unroll
    for (int s = 0; s < SPLITS; s++) {
        m[s] = g_pm[(size_t)s * RTOT + row];
        l[s] = g_pl[(size_t)s * RTOT + row];
    }
    float M = m[0];
#pragma unroll
    for (int s = 1; s < SPLITS; s++) M = fmaxf(M, m[s]);
    float L = 0.f;
#pragma unroll
    for (int s = 0; s < SPLITS; s++) L += l[s] * fast_exp2(m[s] - M);
    float inv = 1.f / L;

    float4 acc[4];
#pragma unroll
    for (int i = 0; i < 4; i++) acc[i] = make_float4(0.f, 0.f, 0.f, 0.f);
#pragma unroll
    for (int s = 0; s < SPLITS; s++) {
        float w = fast_exp2(m[s] - M) * inv;
        const float4* p = (const float4*)(g_po + ((size_t)s * RTOT + row) * Hh + q * 16);
#pragma unroll
        for (int i = 0; i < 4; i++) {
            float4 v = p[i];
            acc[i].x += v.x * w;
            acc[i].y += v.y * w;
            acc[i].z += v.z * w;
            acc[i].w += v.w * w;
        }
    }
    float4* og = (float4*)(out + (size_t)row * Hh + q * 16);
#pragma unroll
    for (int i = 0; i < 4; i++) og[i] = acc[i];
}

extern "C" void kernel_launch(void* const* d_in, const int* in_sizes, int n_in,
                              void* d_out, int out_size)
{
    const float* ini_emb = (const float*)d_in[0];
    const float* wk = (const float*)d_in[1];
    const float* wq = (const float*)d_in[2];
    const float* wv = (const float*)d_in[3];
    float* out = (float*)d_out;

    proj_kernel<<<RTOT / 32, 128>>>(ini_emb, wk, wq, wv);
    flash_kernel<<<dim3(Ss / 64, Bb, SPLITS), 128>>>();
    combine_kernel<<<(RTOT * 4) / 256, 256>>>(out);
}

// round 10
// speedup vs baseline: 7.4221x; 1.0476x over previous
#include <cuda_runtime.h>
#include <cstdint>

#define Bb 4
#define Ss 4096
#define Ee 256
#define Hh 64
#define RTOT (Bb * Ss)

#define SPLITS 4
#define SKEY (Ss / SPLITS)   // 1024 keys per split

// Scratch (device globals: no allocation allowed)
__device__ float g_x[RTOT * Ee];             // RNA-rounded input
__device__ float g_w[3 * Ee * Hh];           // RNA-rounded weights (q,k,v)
__device__ float g_q[RTOT * Hh];
__device__ float g_k[RTOT * Hh];
__device__ float g_v[RTOT * Hh];
__device__ float g_po[SPLITS * RTOT * Hh];   // unnormalized partial O
__device__ float g_pm[SPLITS * RTOT];        // partial row max (log2 domain)
__device__ float g_pl[SPLITS * RTOT];        // partial row sum

__device__ __forceinline__ float fast_exp2(float x) {
    float y;
    asm("ex2.approx.ftz.f32 %0, %1;" : "=f"(y) : "f"(x));
    return y;
}
__device__ __forceinline__ float cvt_tf32(float x) {
    uint32_t u;
    asm("cvt.rna.tf32.f32 %0, %1;" : "=r"(u) : "f"(x));
    return __uint_as_float(u);
}
__device__ __forceinline__ float4 cvt4(float4 v) {
    v.x = cvt_tf32(v.x); v.y = cvt_tf32(v.y);
    v.z = cvt_tf32(v.z); v.w = cvt_tf32(v.w);
    return v;
}
// D(16x8,f32) += A(16x8,tf32) @ B(8x8,tf32 col-major)
__device__ __forceinline__ void mma_tf32(float* d, const float* a, float b0, float b1) {
    asm("mma.sync.aligned.m16n8k8.row.col.f32.tf32.tf32.f32 "
        "{%0,%1,%2,%3}, {%4,%5,%6,%7}, {%8,%9}, {%0,%1,%2,%3};"
        : "+f"(d[0]), "+f"(d[1]), "+f"(d[2]), "+f"(d[3])
        : "r"(__float_as_uint(a[0])), "r"(__float_as_uint(a[1])),
          "r"(__float_as_uint(a[2])), "r"(__float_as_uint(a[3])),
          "r"(__float_as_uint(b0)), "r"(__float_as_uint(b1)));
}
__device__ __forceinline__ void cp16(uint32_t dst, const void* src) {
    asm volatile("cp.async.ca.shared.global [%0], [%1], 16;" :: "r"(dst), "l"(src));
}
__device__ __forceinline__ void cp_commit() {
    asm volatile("cp.async.commit_group;" ::: "memory");
}
template <int N>
__device__ __forceinline__ void cp_wait() {
    asm volatile("cp.async.wait_group %0;" :: "n"(N) : "memory");
}

// ---------------------------------------------------------------------------
// Prep: RNA-round x and weights into g_x / g_w so everything downstream can
// be staged via cp.async with no per-use cvt. 2072 blocks x 256 thr x 2 f4.
// ---------------------------------------------------------------------------
#define XN4 (RTOT * Ee / 4)          // 1048576
#define WN4 (3 * Ee * Hh / 4)        // 12288

__global__ __launch_bounds__(256) void prep_kernel(
    const float* __restrict__ x,
    const float* __restrict__ wk,
    const float* __restrict__ wq,
    const float* __restrict__ wv)
{
    const float4* w4[3] = {(const float4*)wq, (const float4*)wk, (const float4*)wv};
    float4* ox = (float4*)g_x;
    float4* ow = (float4*)g_w;
#pragma unroll
    for (int i = 0; i < 2; i++) {
        int idx = blockIdx.x * 512 + threadIdx.x + i * 256;
        if (idx < XN4) {
            ox[idx] = cvt4(((const float4*)x)[idx]);
        } else {
            int rem = idx - XN4;      // < 12288
            int m = rem >> 12, j = rem & 4095;
            ow[rem] = cvt4(w4[m][j]);
        }
    }
}

// ---------------------------------------------------------------------------
// Projection via tf32 mma, cp.async double-buffered k-passes, split by matrix.
// Grid (256, 3): block = 64 rows x 64 cols of matrix blockIdx.y (q|k|v).
// 256 thr = 8 warps: warp = (row-group w&3) x (col-half w>>2) -> 16r x 32c.
// sX [2][64][36] + sW [2][32][72] = 36.9 KB; strides 36/72 are conflict-free
// (36%32=4 -> 4*gid+tig; 72%32=8 -> gid+8*tig). 8 k-passes of 32.
// Output Q/K/V stored RNA-rounded to tf32 (flash consumes without cvt).
// ---------------------------------------------------------------------------
#define XP 36
#define WP 72
#define XBUF (64 * XP)    // 2304 floats
#define WBUF (32 * WP)    // 2304 floats

__global__ __launch_bounds__(256) void proj_kernel()
{
    __shared__ __align__(16) float sX[2][XBUF];
    __shared__ __align__(16) float sW[2][WBUF];
    const int row0 = blockIdx.x * 64;
    const int m = blockIdx.y;                 // 0=q, 1=k, 2=v
    const int t = threadIdx.x;
    const int warp = t >> 5;
    const int lane = t & 31;
    const int gid = lane >> 2;
    const int tig = lane & 3;
    const int mg = warp & 3;                  // row-group (16 rows)
    const int ch = warp >> 2;                 // col-half (32 cols)

    const float4* xg4 = (const float4*)g_x;
    const float4* wg4 = (const float4*)(g_w + (size_t)m * Ee * Hh);
    const uint32_t sxb = (uint32_t)__cvta_generic_to_shared(&sX[0][0]);
    const uint32_t swb = (uint32_t)__cvta_generic_to_shared(&sW[0][0]);

    float o[4][4];
#pragma unroll
    for (int nt = 0; nt < 4; nt++)
#pragma unroll
        for (int j = 0; j < 4; j++) o[nt][j] = 0.f;

    // stage pass kp into buffer buf: X 512 f4 + W 512 f4 (2 each per thread)
    auto stage = [&](int kp, int buf) {
        const int k0q = kp * 8;
#pragma unroll
        for (int i = 0; i < 2; i++) {
            int idx = t + i * 256;
            int row = idx >> 3, kq = idx & 7;
            cp16(sxb + (uint32_t)(buf * XBUF + row * XP + kq * 4) * 4,
                 xg4 + (size_t)(row0 + row) * 64 + k0q + kq);
        }
#pragma unroll
        for (int i = 0; i < 2; i++) {
            int idx = t + i * 256;
            int k = idx >> 4, cq = idx & 15;
            cp16(swb + (uint32_t)(buf * WBUF + k * WP + cq * 4) * 4,
                 wg4 + (size_t)(kp * 32 + k) * 16 + cq);
        }
    };

    stage(0, 0);
    cp_commit();

    for (int kp = 0; kp < 8; kp++) {
        const int cur = kp & 1;
        if (kp + 1 < 8) {
            stage(kp + 1, cur ^ 1);
            cp_commit();
            cp_wait<1>();
        } else {
            cp_wait<0>();
        }
        __syncthreads();

#pragma unroll
        for (int c = 0; c < 4; c++) {
            float a[4];
            a[0] = sX[cur][(mg * 16 + gid)     * XP + c * 8 + tig];
            a[1] = sX[cur][(mg * 16 + gid + 8) * XP + c * 8 + tig];
            a[2] = sX[cur][(mg * 16 + gid)     * XP + c * 8 + tig + 4];
            a[3] = sX[cur][(mg * 16 + gid + 8) * XP + c * 8 + tig + 4];
#pragma unroll
            for (int nt = 0; nt < 4; nt++) {
                int ncol = ch * 32 + nt * 8 + gid;
                float b0 = sW[cur][ncol + (c * 8 + tig)     * WP];
                float b1 = sW[cur][ncol + (c * 8 + tig + 4) * WP];
                mma_tf32(o[nt], a, b0, b1);
            }
        }
        __syncthreads();
    }

    // epilogue: C frag -> G, RNA-rounded to tf32
    float* G = (m == 0) ? g_q : (m == 1) ? g_k : g_v;
    const int r = row0 + mg * 16 + gid;
#pragma unroll
    for (int nt = 0; nt < 4; nt++) {
        int lcol = ch * 32 + nt * 8 + 2 * tig;
        *(float2*)(&G[(size_t)r * Hh + lcol]) =
            make_float2(cvt_tf32(o[nt][0]), cvt_tf32(o[nt][1]));
        *(float2*)(&G[(size_t)(r + 8) * Hh + lcol]) =
            make_float2(cvt_tf32(o[nt][2]), cvt_tf32(o[nt][3]));
    }
}

// ---------------------------------------------------------------------------
// Flash attention via mma.sync tf32, SPLIT-KV x4, cp.async K/V staging.
// Grid (S/64, B, SPLITS) = 1024 blocks, 128 threads (4 warps x 16 q rows).
// K/V arrive pre-rounded (tf32 values in fp32 containers): no cvt in loop.
// ---------------------------------------------------------------------------
#define BC 32
#define PADK 68
#define PADV 72
#define PADP 36
#define NTILE (SKEY / BC)   // 32
#define KBUFB (BC * PADK * 4)
#define VBUFB (BC * PADV * 4)

__global__ __launch_bounds__(128, 4) void flash_kernel()
{
    __shared__ __align__(16) float sK[2][BC * PADK];
    __shared__ __align__(16) float sV[2][BC * PADV];
    __shared__ __align__(16) float sP[4][16 * PADP];

    const int b = blockIdx.y;
    const int split = blockIdx.z;
    const int t = threadIdx.x;
    const int warp = t >> 5;
    const int lane = t & 31;
    const int gid = lane >> 2;
    const int tig = lane & 3;
    const int row0 = blockIdx.x * 64 + warp * 16;

    const float* qg = g_q + ((size_t)b * Ss + row0) * Hh;
    const float4* kg4 = (const float4*)(g_k + ((size_t)b * Ss + split * SKEY) * Hh);
    const float4* vg4 = (const float4*)(g_v + ((size_t)b * Ss + split * SKEY) * Hh);

    const uint32_t skb = (uint32_t)__cvta_generic_to_shared(&sK[0][0]);
    const uint32_t svb = (uint32_t)__cvta_generic_to_shared(&sV[0][0]);

    const float qscale = 0.0625f * 1.4426950408889634f;

    float qa[8][4];
#pragma unroll
    for (int c = 0; c < 8; c++) {
        qa[c][0] = cvt_tf32(qg[(gid)     * Hh + c * 8 + tig    ] * qscale);
        qa[c][1] = cvt_tf32(qg[(gid + 8) * Hh + c * 8 + tig    ] * qscale);
        qa[c][2] = cvt_tf32(qg[(gid)     * Hh + c * 8 + tig + 4] * qscale);
        qa[c][3] = cvt_tf32(qg[(gid + 8) * Hh + c * 8 + tig + 4] * qscale);
    }

    float o[8][4];
#pragma unroll
    for (int nt = 0; nt < 8; nt++)
#pragma unroll
        for (int j = 0; j < 4; j++) o[nt][j] = 0.f;

    float m0 = -1e30f, m1 = -1e30f;
    float l0 = 0.f, l1 = 0.f;

    // async-stage tile 0 into buffer 0
#pragma unroll
    for (int i = 0; i < 4; i++) {
        int idx = t + i * 128;
        int row = idx >> 4, c4 = idx & 15;
        cp16(skb + (uint32_t)(row * PADK + c4 * 4) * 4, kg4 + idx);
        cp16(svb + (uint32_t)(row * PADV + c4 * 4) * 4, vg4 + idx);
    }
    cp_commit();
    cp_wait<0>();
    __syncthreads();

    for (int tile = 0; tile < NTILE; tile++) {
        const int cur = tile & 1;
        const int nxt = cur ^ 1;

        // async prefetch next tile into the other buffer
        if (tile + 1 < NTILE) {
            const float4* kn = kg4 + (size_t)(tile + 1) * 512;
            const float4* vn = vg4 + (size_t)(tile + 1) * 512;
#pragma unroll
            for (int i = 0; i < 4; i++) {
                int idx = t + i * 128;
                int row = idx >> 4, c4 = idx & 15;
                cp16(skb + nxt * KBUFB + (uint32_t)(row * PADK + c4 * 4) * 4, kn + idx);
                cp16(svb + nxt * VBUFB + (uint32_t)(row * PADV + c4 * 4) * 4, vn + idx);
            }
            cp_commit();
        }

        // ---- S = q @ K^T ----
        float s[4][4];
#pragma unroll
        for (int n = 0; n < 4; n++) {
            s[n][0] = s[n][1] = s[n][2] = s[n][3] = 0.f;
#pragma unroll
            for (int c = 0; c < 8; c++) {
                float b0 = sK[cur][(n * 8 + gid) * PADK + c * 8 + tig];
                float b1 = sK[cur][(n * 8 + gid) * PADK + c * 8 + tig + 4];
                mma_tf32(s[n], qa[c], b0, b1);
            }
        }

        // ---- online softmax ----
        float rmax0 = s[0][0], rmax1 = s[0][2];
#pragma unroll
        for (int n = 0; n < 4; n++) {
            rmax0 = fmaxf(rmax0, fmaxf(s[n][0], s[n][1]));
            rmax1 = fmaxf(rmax1, fmaxf(s[n][2], s[n][3]));
        }
        rmax0 = fmaxf(rmax0, __shfl_xor_sync(0xffffffffu, rmax0, 1));
        rmax0 = fmaxf(rmax0, __shfl_xor_sync(0xffffffffu, rmax0, 2));
        rmax1 = fmaxf(rmax1, __shfl_xor_sync(0xffffffffu, rmax1, 1));
        rmax1 = fmaxf(rmax1, __shfl_xor_sync(0xffffffffu, rmax1, 2));

        float mn0 = fmaxf(m0, rmax0);
        float mn1 = fmaxf(m1, rmax1);
        float corr0 = fast_exp2(m0 - mn0);
        float corr1 = fast_exp2(m1 - mn1);
        m0 = mn0; m1 = mn1;
        l0 *= corr0; l1 *= corr1;
#pragma unroll
        for (int nt = 0; nt < 8; nt++) {
            o[nt][0] *= corr0; o[nt][1] *= corr0;
            o[nt][2] *= corr1; o[nt][3] *= corr1;
        }

        float p[4][4];
#pragma unroll
        for (int n = 0; n < 4; n++) {
            p[n][0] = fast_exp2(s[n][0] - m0);
            p[n][1] = fast_exp2(s[n][1] - m0);
            p[n][2] = fast_exp2(s[n][2] - m1);
            p[n][3] = fast_exp2(s[n][3] - m1);
            l0 += p[n][0] + p[n][1];
            l1 += p[n][2] + p[n][3];
        }

        // ---- stage P (RNA; C-frag -> memory layout) ----
        __syncwarp();
#pragma unroll
        for (int n = 0; n < 4; n++) {
            float2 hi = make_float2(cvt_tf32(p[n][0]), cvt_tf32(p[n][1]));
            float2 lo = make_float2(cvt_tf32(p[n][2]), cvt_tf32(p[n][3]));
            *(float2*)(&sP[warp][(gid)     * PADP + n * 8 + 2 * tig]) = hi;
            *(float2*)(&sP[warp][(gid + 8) * PADP + n * 8 + 2 * tig]) = lo;
        }
        __syncwarp();

        // ---- O += P @ V ----
#pragma unroll
        for (int kc = 0; kc < 4; kc++) {
            float a[4];
            a[0] = sP[warp][(gid)     * PADP + kc * 8 + tig    ];
            a[1] = sP[warp][(gid + 8) * PADP + kc * 8 + tig    ];
            a[2] = sP[warp][(gid)     * PADP + kc * 8 + tig + 4];
            a[3] = sP[warp][(gid + 8) * PADP + kc * 8 + tig + 4];
#pragma unroll
            for (int nt = 0; nt < 8; nt++) {
                float b0 = sV[cur][(kc * 8 + tig)     * PADV + nt * 8 + gid];
                float b1 = sV[cur][(kc * 8 + tig + 4) * PADV + nt * 8 + gid];
                mma_tf32(o[nt], a, b0, b1);
            }
        }

        cp_wait<0>();
        __syncthreads();
    }

    // ---- epilogue: reduce l across quad; write unnormalized partials ----
    l0 += __shfl_xor_sync(0xffffffffu, l0, 1);
    l0 += __shfl_xor_sync(0xffffffffu, l0, 2);
    l1 += __shfl_xor_sync(0xffffffffu, l1, 1);
    l1 += __shfl_xor_sync(0xffffffffu, l1, 2);

    float* po = g_po + ((size_t)split * RTOT + (size_t)b * Ss + row0) * Hh;
#pragma unroll
    for (int nt = 0; nt < 8; nt++) {
        *(float2*)(&po[(gid)     * Hh + nt * 8 + 2 * tig]) = make_float2(o[nt][0], o[nt][1]);
        *(float2*)(&po[(gid + 8) * Hh + nt * 8 + 2 * tig]) = make_float2(o[nt][2], o[nt][3]);
    }
    if (tig == 0) {
        size_t rbase = (size_t)split * RTOT + (size_t)b * Ss + row0;
        g_pm[rbase + gid] = m0;
        g_pm[rbase + gid + 8] = m1;
        g_pl[rbase + gid] = l0;
        g_pl[rbase + gid + 8] = l1;
    }
}

// ---------------------------------------------------------------------------
// Combine: merge SPLITS partials per row. Thread = (row, 16-dim quarter).
// ---------------------------------------------------------------------------
__global__ __launch_bounds__(256) void combine_kernel(float* __restrict__ out)
{
    const int idx = blockIdx.x * 256 + threadIdx.x;
    const int row = idx >> 2;
    const int q = idx & 3;

    float m[SPLITS], l[SPLITS];
#pragma unroll
    for (int s = 0; s < SPLITS; s++) {
        m[s] = g_pm[(size_t)s * RTOT + row];
        l[s] = g_pl[(size_t)s * RTOT + row];
    }
    float M = m[0];
#pragma unroll
    for (int s = 1; s < SPLITS; s++) M = fmaxf(M, m[s]);
    float L = 0.f;
#pragma unroll
    for (int s = 0; s < SPLITS; s++) L += l[s] * fast_exp2(m[s] - M);
    float inv = 1.f / L;

    float4 acc[4];
#pragma unroll
    for (int i = 0; i < 4; i++) acc[i] = make_float4(0.f, 0.f, 0.f, 0.f);
#pragma unroll
    for (int s = 0; s < SPLITS; s++) {
        float w = fast_exp2(m[s] - M) * inv;
        const float4* p = (const float4*)(g_po + ((size_t)s * RTOT + row) * Hh + q * 16);
#pragma unroll
        for (int i = 0; i < 4; i++) {
            float4 v = p[i];
            acc[i].x += v.x * w;
            acc[i].y += v.y * w;
            acc[i].z += v.z * w;
            acc[i].w += v.w * w;
        }
    }
    float4* og = (float4*)(out + (size_t)row * Hh + q * 16);
#pragma unroll
    for (int i = 0; i < 4; i++) og[i] = acc[i];
}

extern "C" void kernel_launch(void* const* d_in, const int* in_sizes, int n_in,
                              void* d_out, int out_size)
{
    const float* ini_emb = (const float*)d_in[0];
    const float* wk = (const float*)d_in[1];
    const float* wq = (const float*)d_in[2];
    const float* wv = (const float*)d_in[3];
    float* out = (float*)d_out;

    prep_kernel<<<(XN4 + WN4) / 512, 256>>>(ini_emb, wk, wq, wv);
    proj_kernel<<<dim3(RTOT / 64, 3), 256>>>();
    flash_kernel<<<dim3(Ss / 64, Bb, SPLITS), 128>>>();
    combine_kernel<<<(RTOT * 4) / 256, 256>>>(out);
}